// round 2
// baseline (speedup 1.0000x reference)
#include <cuda_runtime.h>
#include <math.h>

#define BATCH 16
#define HH 512
#define WW 512
#define WIN 15
#define RAD 7
#define OTR 64
#define OTC 64
#define ITR 78                 // input rows per tile (64 + 14)
#define NCG 8                  // column groups of 8 output cols
#define NJOBS (ITR * NCG)      // 624 horizontal-pass jobs
#define HPA 65                 // pitch of hA in float4 elements (odd -> 4-bank lane stride)
#define HPB 67                 // pitch of hB in floats (stride 3 banks, coprime with 32)
#define NTHREADS 512
#define NBLOCKS 1024

#define SMEM_BYTES (ITR * HPA * 16 + ITR * HPB * 4)   // 81120 + 20904 = 102024

// Per-CTA partials: [cross | I_var | J_var], NBLOCKS each. Written unconditionally
// every call -> no zeroing kernel needed.
__device__ float g_part[3 * NBLOCKS];

extern __shared__ float smem[];

__device__ __forceinline__ void load_pair(const float* __restrict__ rI,
                                          const float* __restrict__ rJ,
                                          int gx, bool rowok,
                                          float& vi, float& vj) {
    bool ok = rowok & (gx >= 0) & (gx < WW);
    vi = ok ? __ldg(rI + gx) : 0.0f;
    vj = ok ? __ldg(rJ + gx) : 0.0f;
}

__global__ void __launch_bounds__(NTHREADS, 2)
ncc_main_kernel(const float* __restrict__ I, const float* __restrict__ J) {
    float4* hA = (float4*)smem;                  // (I, J, II, JJ) horizontal sums
    float*  hB = (float*)(hA + ITR * HPA);       // IJ horizontal sums

    const int tid = threadIdx.x;
    const int b   = blockIdx.z;
    const int gy0 = blockIdx.y * OTR - RAD;
    const int gx0 = blockIdx.x * OTC - RAD;
    const float* __restrict__ Ib = I + (size_t)b * HH * WW;
    const float* __restrict__ Jb = J + (size_t)b * HH * WW;

    // ---- Phase B: fused global load + horizontal 15-tap sliding sums ----
    // job -> (cg, ty); consecutive tid -> consecutive ty (lane stride = one smem
    // row = 1040B for hA = 4 banks -> conflict-free STS.128).
    for (int job = tid; job < NJOBS; job += NTHREADS) {
        const int cg = job / ITR;           // 0..7
        const int ty = job - cg * ITR;      // 0..77
        const int xb = cg * 8;              // first output col of this group
        const int gy = gy0 + ty;
        const bool rowok = (gy >= 0) & (gy < HH);
        const float* rI = Ib + (size_t)(rowok ? gy : 0) * WW;
        const float* rJ = Jb + (size_t)(rowok ? gy : 0) * WW;
        const int gxb = gx0 + xb;

        float aI = 0.f, aJ = 0.f, aII = 0.f, aJJ = 0.f, aIJ = 0.f;
        #pragma unroll
        for (int k = 0; k < WIN; k++) {
            float vi, vj;
            load_pair(rI, rJ, gxb + k, rowok, vi, vj);
            aI += vi; aJ += vj; aII += vi * vi; aJJ += vj * vj; aIJ += vi * vj;
        }
        #pragma unroll
        for (int i = 0; i < 8; i++) {
            hA[ty * HPA + xb + i] = make_float4(aI, aJ, aII, aJJ);
            hB[ty * HPB + xb + i] = aIJ;
            if (i < 7) {
                float ni, nj, oi, oj;
                load_pair(rI, rJ, gxb + i + WIN, rowok, ni, nj);
                load_pair(rI, rJ, gxb + i,       rowok, oi, oj);  // L1 hit
                aI  += ni - oi;
                aJ  += nj - oj;
                aII += ni * ni - oi * oi;
                aJJ += nj * nj - oj * oj;
                aIJ += ni * nj - oi * oj;
            }
        }
    }
    __syncthreads();

    // ---- Phase C: vertical 15-tap sliding sums + combine + accumulate ----
    const int tx    = tid & 63;        // output col
    const int rg    = tid >> 6;        // 0..7 -> rows [rg*8, rg*8+8)
    const int rbase = rg * 8;

    float4 a4 = make_float4(0.f, 0.f, 0.f, 0.f);
    float  aB = 0.f;
    #pragma unroll
    for (int k = 0; k < WIN; k++) {
        float4 v = hA[(rbase + k) * HPA + tx];
        a4.x += v.x; a4.y += v.y; a4.z += v.z; a4.w += v.w;
        aB   += hB[(rbase + k) * HPB + tx];
    }

    const float inv = 1.0f / 225.0f;
    float c_cross = 0.f, c_iv = 0.f, c_jv = 0.f;
    #pragma unroll
    for (int i = 0; i < 8; i++) {
        float SI = a4.x, SJ = a4.y;
        c_cross += aB   - SI * SJ * inv;
        c_iv    += a4.z - SI * SI * inv;
        c_jv    += a4.w - SJ * SJ * inv;
        if (i < 7) {
            float4 vn = hA[(rbase + i + WIN) * HPA + tx];
            float4 vo = hA[(rbase + i) * HPA + tx];
            a4.x += vn.x - vo.x;
            a4.y += vn.y - vo.y;
            a4.z += vn.z - vo.z;
            a4.w += vn.w - vo.w;
            aB   += hB[(rbase + i + WIN) * HPB + tx] - hB[(rbase + i) * HPB + tx];
        }
    }

    // ---- Block reduction -> per-CTA partials ----
    #pragma unroll
    for (int off = 16; off > 0; off >>= 1) {
        c_cross += __shfl_xor_sync(0xFFFFFFFFu, c_cross, off);
        c_iv    += __shfl_xor_sync(0xFFFFFFFFu, c_iv, off);
        c_jv    += __shfl_xor_sync(0xFFFFFFFFu, c_jv, off);
    }
    __syncthreads();                   // all phase-C smem reads done before reuse
    const int lane = tid & 31;
    const int warp = tid >> 5;
    float* red = smem;
    if (lane == 0) {
        red[warp]      = c_cross;
        red[16 + warp] = c_iv;
        red[32 + warp] = c_jv;
    }
    __syncthreads();
    if (tid == 0) {
        double s0 = 0.0, s1 = 0.0, s2 = 0.0;
        #pragma unroll
        for (int w = 0; w < NTHREADS / 32; w++) {
            s0 += (double)red[w];
            s1 += (double)red[16 + w];
            s2 += (double)red[32 + w];
        }
        const int bid = blockIdx.x + (int)gridDim.x * (blockIdx.y + (int)gridDim.y * blockIdx.z);
        g_part[bid]               = (float)s0;
        g_part[NBLOCKS + bid]     = (float)s1;
        g_part[2 * NBLOCKS + bid] = (float)s2;
    }
}

__global__ void __launch_bounds__(1024, 1)
ncc_finalize_kernel(float* __restrict__ out) {
    const int tid = threadIdx.x;
    double c  = (double)g_part[tid];
    double iv = (double)g_part[NBLOCKS + tid];
    double jv = (double)g_part[2 * NBLOCKS + tid];

    #pragma unroll
    for (int off = 16; off > 0; off >>= 1) {
        c  += __shfl_xor_sync(0xFFFFFFFFu, c, off);
        iv += __shfl_xor_sync(0xFFFFFFFFu, iv, off);
        jv += __shfl_xor_sync(0xFFFFFFFFu, jv, off);
    }
    __shared__ double sc[32], si[32], sj[32];
    const int lane = tid & 31;
    const int warp = tid >> 5;
    if (lane == 0) { sc[warp] = c; si[warp] = iv; sj[warp] = jv; }
    __syncthreads();
    if (warp == 0) {
        c  = sc[lane];
        iv = si[lane];
        jv = sj[lane];
        #pragma unroll
        for (int off = 16; off > 0; off >>= 1) {
            c  += __shfl_xor_sync(0xFFFFFFFFu, c, off);
            iv += __shfl_xor_sync(0xFFFFFFFFu, iv, off);
            jv += __shfl_xor_sync(0xFFFFFFFFu, jv, off);
        }
        if (tid == 0) {
            double cc = c / sqrt(iv * jv);
            out[0] = (float)(-cc);
        }
    }
}

extern "C" void kernel_launch(void* const* d_in, const int* in_sizes, int n_in,
                              void* d_out, int out_size) {
    const float* I = (const float*)d_in[0];
    const float* J = (const float*)d_in[1];
    float* out = (float*)d_out;

    cudaFuncSetAttribute(ncc_main_kernel,
                         cudaFuncAttributeMaxDynamicSharedMemorySize, SMEM_BYTES);

    dim3 grid(WW / OTC, HH / OTR, BATCH);   // (8, 8, 16) = 1024 CTAs
    ncc_main_kernel<<<grid, NTHREADS, SMEM_BYTES>>>(I, J);
    ncc_finalize_kernel<<<1, 1024>>>(out);
}

// round 3
// speedup vs baseline: 2.2853x; 2.2853x over previous
#include <cuda_runtime.h>
#include <math.h>

#define BATCH 16
#define HH 512
#define WW 512
#define WIN 15
#define RAD 7
#define OTR 64
#define OTC 64
#define ITR 78                    // 64 + 14 halo rows
#define ITC 78
#define SP2 79                    // raw tile pitch in float2 (632B row stride ≡ 30 banks)
#define HP2 65                    // hS pitch in float2 (520B ≡ 2 banks)
#define NTHREADS 512
#define NBLOCKS 1024
#define NJOBS (ITR * 8)           // 624 horizontal jobs (8-col groups)

#define SMEM_BYTES (ITR * SP2 * 8 + ITR * HP2 * 8)   // 49296 + 40560 = 89856

// Per-CTA partials: [P_II, P_JJ, P_IJ, S_II, S_JJ, S_IJ], padded to 8 doubles.
__device__ double g_part[NBLOCKS][8];
__device__ unsigned int g_count = 0;

extern __shared__ float2 smem2[];

__global__ void __launch_bounds__(NTHREADS, 2)
ncc_main(const float* __restrict__ I, const float* __restrict__ J,
         float* __restrict__ out) {
    float2* s2 = smem2;                 // raw (I,J) halo tile, 78 x 78 (pitch 79)
    float2* hS = smem2 + ITR * SP2;     // horizontal (I_sum, J_sum), 78 x 64 (pitch 65)

    const int tid = threadIdx.x;
    const int b   = blockIdx.z;
    const int gy0 = blockIdx.y * OTR - RAD;
    const int gx0 = blockIdx.x * OTC - RAD;
    const float* __restrict__ Ib = I + (size_t)b * HH * WW;
    const float* __restrict__ Jb = J + (size_t)b * HH * WW;

    // ---- Phase A: coalesced load of 78x78 halo + weighted pointwise sums ----
    float pII = 0.f, pJJ = 0.f, pIJ = 0.f;
    for (int idx = tid; idx < ITR * ITC; idx += NTHREADS) {
        const int ty = idx / ITC;
        const int tx = idx - ty * ITC;
        const int gy = gy0 + ty;
        const int gx = gx0 + tx;
        float vi = 0.f, vj = 0.f;
        if (gy >= 0 && gy < HH && gx >= 0 && gx < WW) {
            const int g = gy * WW + gx;
            vi = __ldg(Ib + g);
            vj = __ldg(Jb + g);
        }
        s2[ty * SP2 + tx] = make_float2(vi, vj);
        // Owned pixel (counted exactly once across the grid): interior of tile.
        if ((unsigned)(ty - RAD) < OTR && (unsigned)(tx - RAD) < OTC) {
            const int wy = min(gy + RAD, HH - 1) - max(gy - RAD, 0) + 1;
            const int wx = min(gx + RAD, WW - 1) - max(gx - RAD, 0) + 1;
            const float w = (float)(wy * wx);
            pII += w * vi * vi;
            pJJ += w * vj * vj;
            pIJ += w * vi * vj;
        }
    }
    __syncthreads();

    // ---- Phase B: horizontal 15-tap sliding (I_sum, J_sum) only ----
    for (int job = tid; job < NJOBS; job += NTHREADS) {
        const int cg = job / ITR;
        const int ty = job - cg * ITR;       // lanes -> consecutive ty
        const int xb = cg * 8;
        const float2* r = s2 + ty * SP2;
        float aI = 0.f, aJ = 0.f;
        #pragma unroll
        for (int k = 0; k < WIN; k++) {
            float2 v = r[xb + k];
            aI += v.x; aJ += v.y;
        }
        #pragma unroll
        for (int i = 0; i < 8; i++) {
            hS[ty * HP2 + xb + i] = make_float2(aI, aJ);
            if (i < 7) {
                float2 vn = r[xb + i + WIN];
                float2 vo = r[xb + i];
                aI += vn.x - vo.x;
                aJ += vn.y - vo.y;
            }
        }
    }
    __syncthreads();

    // ---- Phase C: vertical 15-tap sliding + quadratic accumulation ----
    const int tx    = tid & 63;
    const int rbase = (tid >> 6) * 8;
    float aSI = 0.f, aSJ = 0.f;
    #pragma unroll
    for (int k = 0; k < WIN; k++) {
        float2 v = hS[(rbase + k) * HP2 + tx];
        aSI += v.x; aSJ += v.y;
    }
    float sII = 0.f, sJJ = 0.f, sIJ = 0.f;
    #pragma unroll
    for (int i = 0; i < 8; i++) {
        sII += aSI * aSI;
        sJJ += aSJ * aSJ;
        sIJ += aSI * aSJ;
        if (i < 7) {
            float2 vn = hS[(rbase + i + WIN) * HP2 + tx];
            float2 vo = hS[(rbase + i) * HP2 + tx];
            aSI += vn.x - vo.x;
            aSJ += vn.y - vo.y;
        }
    }

    // ---- Per-CTA reduction (double) ----
    double a0 = (double)pII, a1 = (double)pJJ, a2 = (double)pIJ;
    double a3 = (double)sII, a4 = (double)sJJ, a5 = (double)sIJ;
    #pragma unroll
    for (int off = 16; off > 0; off >>= 1) {
        a0 += __shfl_xor_sync(0xFFFFFFFFu, a0, off);
        a1 += __shfl_xor_sync(0xFFFFFFFFu, a1, off);
        a2 += __shfl_xor_sync(0xFFFFFFFFu, a2, off);
        a3 += __shfl_xor_sync(0xFFFFFFFFu, a3, off);
        a4 += __shfl_xor_sync(0xFFFFFFFFu, a4, off);
        a5 += __shfl_xor_sync(0xFFFFFFFFu, a5, off);
    }
    __syncthreads();                         // phase-C smem reads done before reuse
    double* red = (double*)smem2;            // 16 warps x 6 doubles
    const int lane = tid & 31;
    const int warp = tid >> 5;
    if (lane == 0) {
        red[warp * 6 + 0] = a0; red[warp * 6 + 1] = a1; red[warp * 6 + 2] = a2;
        red[warp * 6 + 3] = a3; red[warp * 6 + 4] = a4; red[warp * 6 + 5] = a5;
    }
    __syncthreads();

    const int bid = blockIdx.x + (int)gridDim.x * (blockIdx.y + (int)gridDim.y * blockIdx.z);
    __shared__ int s_last;
    if (tid == 0) {
        double t0 = 0, t1 = 0, t2 = 0, t3 = 0, t4 = 0, t5 = 0;
        #pragma unroll
        for (int w = 0; w < NTHREADS / 32; w++) {
            t0 += red[w * 6 + 0]; t1 += red[w * 6 + 1]; t2 += red[w * 6 + 2];
            t3 += red[w * 6 + 3]; t4 += red[w * 6 + 4]; t5 += red[w * 6 + 5];
        }
        g_part[bid][0] = t0; g_part[bid][1] = t1; g_part[bid][2] = t2;
        g_part[bid][3] = t3; g_part[bid][4] = t4; g_part[bid][5] = t5;
        __threadfence();
        unsigned int prev = atomicAdd(&g_count, 1u);
        s_last = (prev == NBLOCKS - 1);
    }
    __syncthreads();

    // ---- Last CTA: global reduction + finalize ----
    if (s_last) {
        double c0 = 0, c1 = 0, c2 = 0, c3 = 0, c4 = 0, c5 = 0;
        for (int c = tid; c < NBLOCKS; c += NTHREADS) {
            c0 += g_part[c][0]; c1 += g_part[c][1]; c2 += g_part[c][2];
            c3 += g_part[c][3]; c4 += g_part[c][4]; c5 += g_part[c][5];
        }
        #pragma unroll
        for (int off = 16; off > 0; off >>= 1) {
            c0 += __shfl_xor_sync(0xFFFFFFFFu, c0, off);
            c1 += __shfl_xor_sync(0xFFFFFFFFu, c1, off);
            c2 += __shfl_xor_sync(0xFFFFFFFFu, c2, off);
            c3 += __shfl_xor_sync(0xFFFFFFFFu, c3, off);
            c4 += __shfl_xor_sync(0xFFFFFFFFu, c4, off);
            c5 += __shfl_xor_sync(0xFFFFFFFFu, c5, off);
        }
        __syncthreads();
        if (lane == 0) {
            red[warp * 6 + 0] = c0; red[warp * 6 + 1] = c1; red[warp * 6 + 2] = c2;
            red[warp * 6 + 3] = c3; red[warp * 6 + 4] = c4; red[warp * 6 + 5] = c5;
        }
        __syncthreads();
        if (tid == 0) {
            double t0 = 0, t1 = 0, t2 = 0, t3 = 0, t4 = 0, t5 = 0;
            #pragma unroll
            for (int w = 0; w < NTHREADS / 32; w++) {
                t0 += red[w * 6 + 0]; t1 += red[w * 6 + 1]; t2 += red[w * 6 + 2];
                t3 += red[w * 6 + 3]; t4 += red[w * 6 + 4]; t5 += red[w * 6 + 5];
            }
            const double inv = 1.0 / 225.0;
            double cross = t2 - t5 * inv;
            double iv    = t0 - t3 * inv;
            double jv    = t1 - t4 * inv;
            out[0] = (float)(-(cross / sqrt(iv * jv)));
            g_count = 0;                      // reset for next graph replay
        }
    }
}

extern "C" void kernel_launch(void* const* d_in, const int* in_sizes, int n_in,
                              void* d_out, int out_size) {
    const float* I = (const float*)d_in[0];
    const float* J = (const float*)d_in[1];
    float* out = (float*)d_out;

    cudaFuncSetAttribute(ncc_main,
                         cudaFuncAttributeMaxDynamicSharedMemorySize, SMEM_BYTES);
    dim3 grid(WW / OTC, HH / OTR, BATCH);   // (8, 8, 16) = 1024 CTAs
    ncc_main<<<grid, NTHREADS, SMEM_BYTES>>>(I, J, out);
}

// round 4
// speedup vs baseline: 3.0155x; 1.3195x over previous
#include <cuda_runtime.h>
#include <math.h>

#define BATCH 16
#define HH 512
#define WW 512
#define WIN 15
#define RAD 7
#define OTR 64
#define OTC 64
#define ITR 78                    // 64 + 14 halo rows
#define ITC 78
#define SP2 79                    // raw tile pitch in float2
#define HP2 65                    // hS pitch in float2
#define NTHREADS 256
#define NBLOCKS 1024
#define NJOBS (ITR * 8)           // 624 horizontal jobs (8-col groups)

#define SMEM_BYTES (ITR * SP2 * 8 + ITR * HP2 * 8)   // 49296 + 40560 = 89856

// Per-CTA partials: [P_II, P_JJ, P_IJ, S_II, S_JJ, S_IJ], padded to 8 doubles.
__device__ double g_part[NBLOCKS][8];
__device__ unsigned int g_count = 0;

extern __shared__ float2 smem2[];

__global__ void __launch_bounds__(NTHREADS, 2)
ncc_main(const float* __restrict__ I, const float* __restrict__ J,
         float* __restrict__ out) {
    float2* s2 = smem2;                 // raw (I,J) halo tile, 78 x 78 (pitch 79)
    float2* hS = smem2 + ITR * SP2;     // horizontal (I_sum, J_sum), 78 x 64 (pitch 65)

    const int tid = threadIdx.x;
    const int b   = blockIdx.z;
    const int gy0 = blockIdx.y * OTR - RAD;
    const int gx0 = blockIdx.x * OTC - RAD;
    const float* __restrict__ Ib = I + (size_t)b * HH * WW;
    const float* __restrict__ Jb = J + (size_t)b * HH * WW;

    // ---- Phase A: coalesced load of 78x78 halo + weighted pointwise sums ----
    float pII = 0.f, pJJ = 0.f, pIJ = 0.f;
    for (int idx = tid; idx < ITR * ITC; idx += NTHREADS) {
        const int ty = idx / ITC;            // const divisor -> mul/shift
        const int tx = idx - ty * ITC;
        const int gy = gy0 + ty;
        const int gx = gx0 + tx;
        float vi = 0.f, vj = 0.f;
        if (gy >= 0 && gy < HH && gx >= 0 && gx < WW) {
            const int g = gy * WW + gx;
            vi = __ldg(Ib + g);
            vj = __ldg(Jb + g);
        }
        s2[ty * SP2 + tx] = make_float2(vi, vj);
        // Owned pixel (interior of tile) -> weighted quadratic sums.
        if ((unsigned)(ty - RAD) < OTR && (unsigned)(tx - RAD) < OTC) {
            const int wy = min(gy + RAD, HH - 1) - max(gy - RAD, 0) + 1;
            const int wx = min(gx + RAD, WW - 1) - max(gx - RAD, 0) + 1;
            const float w = (float)(wy * wx);
            pII += w * vi * vi;
            pJJ += w * vj * vj;
            pIJ += w * vi * vj;
        }
    }
    __syncthreads();

    // ---- Phase B: horizontal 15-tap sliding (I_sum, J_sum) only ----
    for (int job = tid; job < NJOBS; job += NTHREADS) {
        const int cg = job / ITR;
        const int ty = job - cg * ITR;       // consecutive lanes -> consecutive ty
        const int xb = cg * 8;
        const float2* r = s2 + ty * SP2;
        float aI = 0.f, aJ = 0.f;
        #pragma unroll
        for (int k = 0; k < WIN; k++) {
            float2 v = r[xb + k];
            aI += v.x; aJ += v.y;
        }
        #pragma unroll
        for (int i = 0; i < 8; i++) {
            hS[ty * HP2 + xb + i] = make_float2(aI, aJ);
            if (i < 7) {
                float2 vn = r[xb + i + WIN];
                float2 vo = r[xb + i];
                aI += vn.x - vo.x;
                aJ += vn.y - vo.y;
            }
        }
    }
    __syncthreads();

    // ---- Phase C: vertical 15-tap sliding + quadratic accumulation ----
    // 256 threads: tx = col (0..63), rg = 0..3 -> 16 output rows each.
    const int tx    = tid & 63;
    const int rbase = (tid >> 6) * 16;
    float aSI = 0.f, aSJ = 0.f;
    #pragma unroll
    for (int k = 0; k < WIN; k++) {
        float2 v = hS[(rbase + k) * HP2 + tx];
        aSI += v.x; aSJ += v.y;
    }
    float sII = 0.f, sJJ = 0.f, sIJ = 0.f;
    #pragma unroll
    for (int i = 0; i < 16; i++) {
        sII += aSI * aSI;
        sJJ += aSJ * aSJ;
        sIJ += aSI * aSJ;
        if (i < 15) {
            float2 vn = hS[(rbase + i + WIN) * HP2 + tx];
            float2 vo = hS[(rbase + i) * HP2 + tx];
            aSI += vn.x - vo.x;
            aSJ += vn.y - vo.y;
        }
    }

    // ---- Per-CTA reduction (double) ----
    double a0 = (double)pII, a1 = (double)pJJ, a2 = (double)pIJ;
    double a3 = (double)sII, a4 = (double)sJJ, a5 = (double)sIJ;
    #pragma unroll
    for (int off = 16; off > 0; off >>= 1) {
        a0 += __shfl_xor_sync(0xFFFFFFFFu, a0, off);
        a1 += __shfl_xor_sync(0xFFFFFFFFu, a1, off);
        a2 += __shfl_xor_sync(0xFFFFFFFFu, a2, off);
        a3 += __shfl_xor_sync(0xFFFFFFFFu, a3, off);
        a4 += __shfl_xor_sync(0xFFFFFFFFu, a4, off);
        a5 += __shfl_xor_sync(0xFFFFFFFFu, a5, off);
    }
    __syncthreads();                         // all phase-C smem reads done before reuse
    double* red = (double*)smem2;            // 8 warps x 6 doubles
    const int lane = tid & 31;
    const int warp = tid >> 5;
    if (lane == 0) {
        red[warp * 6 + 0] = a0; red[warp * 6 + 1] = a1; red[warp * 6 + 2] = a2;
        red[warp * 6 + 3] = a3; red[warp * 6 + 4] = a4; red[warp * 6 + 5] = a5;
    }
    __syncthreads();

    const int bid = blockIdx.x + (int)gridDim.x * (blockIdx.y + (int)gridDim.y * blockIdx.z);
    __shared__ int s_last;
    if (tid == 0) {
        double t0 = 0, t1 = 0, t2 = 0, t3 = 0, t4 = 0, t5 = 0;
        #pragma unroll
        for (int w = 0; w < NTHREADS / 32; w++) {
            t0 += red[w * 6 + 0]; t1 += red[w * 6 + 1]; t2 += red[w * 6 + 2];
            t3 += red[w * 6 + 3]; t4 += red[w * 6 + 4]; t5 += red[w * 6 + 5];
        }
        g_part[bid][0] = t0; g_part[bid][1] = t1; g_part[bid][2] = t2;
        g_part[bid][3] = t3; g_part[bid][4] = t4; g_part[bid][5] = t5;
        __threadfence();
        unsigned int prev = atomicAdd(&g_count, 1u);
        s_last = (prev == NBLOCKS - 1);
    }
    __syncthreads();

    // ---- Last CTA: global reduction + finalize ----
    if (s_last) {
        double c0 = 0, c1 = 0, c2 = 0, c3 = 0, c4 = 0, c5 = 0;
        for (int c = tid; c < NBLOCKS; c += NTHREADS) {
            c0 += g_part[c][0]; c1 += g_part[c][1]; c2 += g_part[c][2];
            c3 += g_part[c][3]; c4 += g_part[c][4]; c5 += g_part[c][5];
        }
        #pragma unroll
        for (int off = 16; off > 0; off >>= 1) {
            c0 += __shfl_xor_sync(0xFFFFFFFFu, c0, off);
            c1 += __shfl_xor_sync(0xFFFFFFFFu, c1, off);
            c2 += __shfl_xor_sync(0xFFFFFFFFu, c2, off);
            c3 += __shfl_xor_sync(0xFFFFFFFFu, c3, off);
            c4 += __shfl_xor_sync(0xFFFFFFFFu, c4, off);
            c5 += __shfl_xor_sync(0xFFFFFFFFu, c5, off);
        }
        __syncthreads();
        if (lane == 0) {
            red[warp * 6 + 0] = c0; red[warp * 6 + 1] = c1; red[warp * 6 + 2] = c2;
            red[warp * 6 + 3] = c3; red[warp * 6 + 4] = c4; red[warp * 6 + 5] = c5;
        }
        __syncthreads();
        if (tid == 0) {
            double t0 = 0, t1 = 0, t2 = 0, t3 = 0, t4 = 0, t5 = 0;
            #pragma unroll
            for (int w = 0; w < NTHREADS / 32; w++) {
                t0 += red[w * 6 + 0]; t1 += red[w * 6 + 1]; t2 += red[w * 6 + 2];
                t3 += red[w * 6 + 3]; t4 += red[w * 6 + 4]; t5 += red[w * 6 + 5];
            }
            const double inv = 1.0 / 225.0;
            double cross = t2 - t5 * inv;
            double iv    = t0 - t3 * inv;
            double jv    = t1 - t4 * inv;
            out[0] = (float)(-(cross / sqrt(iv * jv)));
            g_count = 0;                      // reset for next graph replay
        }
    }
}

extern "C" void kernel_launch(void* const* d_in, const int* in_sizes, int n_in,
                              void* d_out, int out_size) {
    const float* I = (const float*)d_in[0];
    const float* J = (const float*)d_in[1];
    float* out = (float*)d_out;

    cudaFuncSetAttribute(ncc_main,
                         cudaFuncAttributeMaxDynamicSharedMemorySize, SMEM_BYTES);
    dim3 grid(WW / OTC, HH / OTR, BATCH);   // (8, 8, 16) = 1024 CTAs
    ncc_main<<<grid, NTHREADS, SMEM_BYTES>>>(I, J, out);
}

// round 5
// speedup vs baseline: 5.1680x; 1.7138x over previous
#include <cuda_runtime.h>
#include <math.h>

#define BATCH 16
#define HH 512
#define WW 512
#define WIN 15
#define RAD 7
#define OTC 114                 // output cols per tile
#define WINC 128                // input cols per tile (OTC + 14)
#define OTR 64                  // output rows per tile
#define GRX 5                   // ceil(512/114)
#define GRY 8                   // 512/64
#define NT 256
#define NBLOCKS (GRX * GRY * BATCH)   // 640
#define VP 129                  // vS pitch in float2

#define SMEM_BYTES (OTR * VP * 8)     // 64*129*8 = 66048

__device__ double g_part[NBLOCKS][8];
__device__ unsigned int g_count = 0;

extern __shared__ float2 smem2[];

__global__ void __launch_bounds__(NT, 3)
ncc_main(const float* __restrict__ I, const float* __restrict__ J,
         float* __restrict__ out) {
    float2* vS = smem2;   // vertical (I_sum, J_sum): 64 rows x 128 cols, pitch 129

    const int tid = threadIdx.x;
    const int bx = blockIdx.x, by = blockIdx.y, bz = blockIdx.z;
    const float* __restrict__ Ib = I + (size_t)bz * HH * WW;
    const float* __restrict__ Jb = J + (size_t)bz * HH * WW;

    // ================= Phase A: vertical 15-tap sliding in registers =========
    // 2 row-groups x 128 columns. Thread streams 46 input rows of one column.
    {
        const int tx      = tid & 127;
        const int g       = tid >> 7;
        const int outbase = by * OTR + g * 32;    // first owned output row
        const int rowbase = outbase - RAD;        // first input row
        const int gx      = bx * OTC - RAD + tx;
        const bool colok  = (gx >= 0) && (gx < WW);
        const bool ownx   = colok && (tx >= RAD) && (tx < RAD + OTC);
        float wx = 0.f;
        if (ownx) wx = (float)(min(gx + RAD, WW - 1) - max(gx - RAD, 0) + 1);

        float2 ring[WIN];
        float vI = 0.f, vJ = 0.f;
        float pII = 0.f, pJJ = 0.f, pIJ = 0.f;

        #pragma unroll
        for (int r = 0; r < 46; r++) {
            const int gy = rowbase + r;
            float vi = 0.f, vj = 0.f;
            if (colok && gy >= 0 && gy < HH) {
                const int gidx = gy * WW + gx;
                vi = __ldg(Ib + gidx);
                vj = __ldg(Jb + gidx);
            }
            if (r >= WIN) {
                float2 o = ring[r % WIN];
                vI -= o.x; vJ -= o.y;
            }
            ring[r % WIN] = make_float2(vi, vj);
            vI += vi; vJ += vj;

            // Owned input pixel: rows [outbase, outbase+32), owned column.
            if (r >= RAD && r < RAD + 32 && ownx) {
                const float wy = (float)(min(gy + RAD, HH - 1) - max(gy - RAD, 0) + 1);
                const float w = wy * wx;
                pII += w * vi * vi;
                pJJ += w * vj * vj;
                pIJ += w * vi * vj;
            }
            if (r >= WIN - 1) {
                vS[(g * 32 + r - (WIN - 1)) * VP + tx] = make_float2(vI, vJ);
            }
        }
        // carry pointwise partials into phase B accumulators via shared regs
        // (kept live; folded into reduction below)
        __syncthreads();

        // ============= Phase B: horizontal 15-tap slide + quadratics =========
        const int row = tid >> 2;          // 0..63
        const int q   = tid & 3;
        const int oc0 = q * 29;            // col groups: 29,29,29,27
        const int ncols = min(OTC, WW - bx * OTC);   // 114 or 56 (tile 4)
        const float2* vrow = vS + row * VP;

        float aSI = 0.f, aSJ = 0.f;
        #pragma unroll
        for (int k = 0; k < WIN; k++) {
            float2 v = vrow[oc0 + k];
            aSI += v.x; aSJ += v.y;
        }
        float sII = 0.f, sJJ = 0.f, sIJ = 0.f;
        #pragma unroll
        for (int i = 0; i < 29; i++) {
            const int oc = oc0 + i;
            if (oc < ncols) {
                sII += aSI * aSI;
                sJJ += aSJ * aSJ;
                sIJ += aSI * aSJ;
            }
            if (i < 28 && oc < OTC - 1) {      // window stays inside 128 input cols
                float2 vn = vrow[oc + WIN];
                float2 vo = vrow[oc];
                aSI += vn.x - vo.x;
                aSJ += vn.y - vo.y;
            }
        }

        // ===================== Per-CTA reduction (double) ====================
        double a0 = (double)pII, a1 = (double)pJJ, a2 = (double)pIJ;
        double a3 = (double)sII, a4 = (double)sJJ, a5 = (double)sIJ;
        #pragma unroll
        for (int off = 16; off > 0; off >>= 1) {
            a0 += __shfl_xor_sync(0xFFFFFFFFu, a0, off);
            a1 += __shfl_xor_sync(0xFFFFFFFFu, a1, off);
            a2 += __shfl_xor_sync(0xFFFFFFFFu, a2, off);
            a3 += __shfl_xor_sync(0xFFFFFFFFu, a3, off);
            a4 += __shfl_xor_sync(0xFFFFFFFFu, a4, off);
            a5 += __shfl_xor_sync(0xFFFFFFFFu, a5, off);
        }
        __syncthreads();                       // all phase-B smem reads done
        double* red = (double*)smem2;          // 8 warps x 6 doubles
        const int lane = tid & 31;
        const int warp = tid >> 5;
        if (lane == 0) {
            red[warp * 6 + 0] = a0; red[warp * 6 + 1] = a1; red[warp * 6 + 2] = a2;
            red[warp * 6 + 3] = a3; red[warp * 6 + 4] = a4; red[warp * 6 + 5] = a5;
        }
        __syncthreads();

        const int bid = bx + GRX * (by + GRY * bz);
        __shared__ int s_last;
        if (tid == 0) {
            double t0 = 0, t1 = 0, t2 = 0, t3 = 0, t4 = 0, t5 = 0;
            #pragma unroll
            for (int w = 0; w < NT / 32; w++) {
                t0 += red[w * 6 + 0]; t1 += red[w * 6 + 1]; t2 += red[w * 6 + 2];
                t3 += red[w * 6 + 3]; t4 += red[w * 6 + 4]; t5 += red[w * 6 + 5];
            }
            g_part[bid][0] = t0; g_part[bid][1] = t1; g_part[bid][2] = t2;
            g_part[bid][3] = t3; g_part[bid][4] = t4; g_part[bid][5] = t5;
            __threadfence();
            unsigned int prev = atomicAdd(&g_count, 1u);
            s_last = (prev == NBLOCKS - 1);
        }
        __syncthreads();

        // ================= Last CTA: global reduce + finalize =================
        if (s_last) {
            double c0 = 0, c1 = 0, c2 = 0, c3 = 0, c4 = 0, c5 = 0;
            for (int c = tid; c < NBLOCKS; c += NT) {
                c0 += g_part[c][0]; c1 += g_part[c][1]; c2 += g_part[c][2];
                c3 += g_part[c][3]; c4 += g_part[c][4]; c5 += g_part[c][5];
            }
            #pragma unroll
            for (int off = 16; off > 0; off >>= 1) {
                c0 += __shfl_xor_sync(0xFFFFFFFFu, c0, off);
                c1 += __shfl_xor_sync(0xFFFFFFFFu, c1, off);
                c2 += __shfl_xor_sync(0xFFFFFFFFu, c2, off);
                c3 += __shfl_xor_sync(0xFFFFFFFFu, c3, off);
                c4 += __shfl_xor_sync(0xFFFFFFFFu, c4, off);
                c5 += __shfl_xor_sync(0xFFFFFFFFu, c5, off);
            }
            __syncthreads();
            if (lane == 0) {
                red[warp * 6 + 0] = c0; red[warp * 6 + 1] = c1; red[warp * 6 + 2] = c2;
                red[warp * 6 + 3] = c3; red[warp * 6 + 4] = c4; red[warp * 6 + 5] = c5;
            }
            __syncthreads();
            if (tid == 0) {
                double t0 = 0, t1 = 0, t2 = 0, t3 = 0, t4 = 0, t5 = 0;
                #pragma unroll
                for (int w = 0; w < NT / 32; w++) {
                    t0 += red[w * 6 + 0]; t1 += red[w * 6 + 1]; t2 += red[w * 6 + 2];
                    t3 += red[w * 6 + 3]; t4 += red[w * 6 + 4]; t5 += red[w * 6 + 5];
                }
                const double inv = 1.0 / 225.0;
                double cross = t2 - t5 * inv;
                double iv    = t0 - t3 * inv;
                double jv    = t1 - t4 * inv;
                out[0] = (float)(-(cross / sqrt(iv * jv)));
                g_count = 0;    // reset for next graph replay
            }
        }
    }
}

extern "C" void kernel_launch(void* const* d_in, const int* in_sizes, int n_in,
                              void* d_out, int out_size) {
    const float* I = (const float*)d_in[0];
    const float* J = (const float*)d_in[1];
    float* out = (float*)d_out;

    cudaFuncSetAttribute(ncc_main,
                         cudaFuncAttributeMaxDynamicSharedMemorySize, SMEM_BYTES);
    dim3 grid(GRX, GRY, BATCH);   // (5, 8, 16) = 640 CTAs
    ncc_main<<<grid, NT, SMEM_BYTES>>>(I, J, out);
}